// round 3
// baseline (speedup 1.0000x reference)
#include <cuda_runtime.h>
#include <cstdint>

#define BB 2
#define SS 2048
#define DD 1024
#define HH 16
#define DHD 64
#define NROWS (BB*SS)          // 4096
#define OUT_ELEMS (BB*SS*DD)   // 4194304
#define ATTN_ELEMS (HH*BB*SS*SS) // 134217728

// ---------------- scratch (device globals: allowed) ----------------
__device__ float g_q[NROWS * DD];
__device__ float g_k[NROWS * DD];
__device__ float g_v[NROWS * DD];
__device__ float g_concat[NROWS * DD];

// =====================================================================
// Kernel 1: per-head projections as one big GEMM per tensor.
//   C[(b*S+s)*1024 + h*64+e] = sum_d In[(b*S+s)*1024+d] * W[h,d,e]
// 128x128 tile, BK=8, 256 threads, 8x8 per-thread register tile.
// =====================================================================
__global__ __launch_bounds__(256) void gemm_proj(
    const float* __restrict__ q_in, const float* __restrict__ k_in,
    const float* __restrict__ v_in,
    const float* __restrict__ Wq, const float* __restrict__ Wk,
    const float* __restrict__ Wv)
{
    const int z = blockIdx.z;
    const float* A = (z == 0) ? q_in : ((z == 1) ? k_in : v_in);
    const float* W = (z == 0) ? Wq   : ((z == 1) ? Wk   : Wv);
    float* C       = (z == 0) ? g_q  : ((z == 1) ? g_k  : g_v);

    __shared__ float As[8][128];
    __shared__ float Bs[8][128];

    const int tid  = threadIdx.x;
    const int row0 = blockIdx.x << 7;
    const int col0 = blockIdx.y << 7;
    const int tx = tid & 15, ty = tid >> 4;
    const int m0 = ty << 3, n0 = tx << 3;

    // A loader: 128 rows x 8 k, one float4 per thread
    const int lm = tid >> 1;
    const int lk = (tid & 1) << 2;
    // B loader: 8 k rows x 128 n, one float4 per thread
    const int bk = tid >> 5;
    const int bn = (tid & 31) << 2;

    float acc[8][8] = {};

    for (int k0 = 0; k0 < DD; k0 += 8) {
        float4 av = *(const float4*)&A[(size_t)(row0 + lm) * DD + k0 + lk];
        As[lk + 0][lm] = av.x; As[lk + 1][lm] = av.y;
        As[lk + 2][lm] = av.z; As[lk + 3][lm] = av.w;

        const int n = col0 + bn;
        // W[h,d,e] with h = n>>6, e = n&63, d = k0+bk
        const int widx = ((n >> 6) * DD + (k0 + bk)) * DHD + (n & 63);
        *(float4*)&Bs[bk][bn] = *(const float4*)&W[widx];
        __syncthreads();

        #pragma unroll
        for (int k = 0; k < 8; k++) {
            float a[8], b[8];
            *(float4*)&a[0] = *(const float4*)&As[k][m0];
            *(float4*)&a[4] = *(const float4*)&As[k][m0 + 4];
            *(float4*)&b[0] = *(const float4*)&Bs[k][n0];
            *(float4*)&b[4] = *(const float4*)&Bs[k][n0 + 4];
            #pragma unroll
            for (int i = 0; i < 8; i++)
                #pragma unroll
                for (int j = 0; j < 8; j++)
                    acc[i][j] = fmaf(a[i], b[j], acc[i][j]);
        }
        __syncthreads();
    }

    #pragma unroll
    for (int i = 0; i < 8; i++) {
        float* crow = &C[(size_t)(row0 + m0 + i) * DD + col0 + n0];
        *(float4*)&crow[0] = make_float4(acc[i][0], acc[i][1], acc[i][2], acc[i][3]);
        *(float4*)&crow[4] = make_float4(acc[i][4], acc[i][5], acc[i][6], acc[i][7]);
    }
}

// =====================================================================
// Kernel 2: fused attention per (h, b, 16-row tile).
//  Phase A: scores rows (16 x 2048) into smem, K staged in 256x64 tiles.
//  Softmax in smem (warp per 2 rows), optional global attn write.
//  Phase C: weighted = P @ V with V staged in 256x64 tiles, t-split x4.
// =====================================================================
__global__ __launch_bounds__(256) void attn_kernel(float* __restrict__ attn_out)
{
    extern __shared__ float smem[];
    float* sc = smem;                      // 16 * 2048
    float* kv = smem + 16 * SS;            // 256 * 65 (K) / 256 * 64 (V)
    float* Qs = kv + 256 * 65;             // 16 * 64

    const int tid = threadIdx.x;
    const int s0 = blockIdx.x << 4;
    const int b  = blockIdx.y;
    const int h  = blockIdx.z;

    const float* qg = g_q + (size_t)(b * SS) * DD + h * DHD;
    const float* kg = g_k + (size_t)(b * SS) * DD + h * DHD;
    const float* vg = g_v + (size_t)(b * SS) * DD + h * DHD;

    // ---- load Q tile: 16 rows x 64 ----
    {
        const int r  = tid >> 4;
        const int e0 = (tid & 15) << 2;
        *(float4*)&Qs[r * DHD + e0] = *(const float4*)&qg[(size_t)(s0 + r) * DD + e0];
    }
    __syncthreads();

    // ---- Phase A: scores ----
    {
        const int r0 = (tid >> 6) << 2;    // 0,4,8,12
        const int j0 = tid & 63;
        for (int t0 = 0; t0 < SS; t0 += 256) {
            #pragma unroll
            for (int it = 0; it < 16; it++) {
                const int j  = (it << 4) + (tid >> 4);
                const int e0 = (tid & 15) << 2;
                float4 t = *(const float4*)&kg[(size_t)(t0 + j) * DD + e0];
                float* dst = &kv[j * 65 + e0];
                dst[0] = t.x; dst[1] = t.y; dst[2] = t.z; dst[3] = t.w;
            }
            __syncthreads();

            float acc[4][4] = {};
            #pragma unroll 8
            for (int e = 0; e < 64; e++) {
                float q[4];
                #pragma unroll
                for (int i = 0; i < 4; i++) q[i] = Qs[(r0 + i) * DHD + e];
                #pragma unroll
                for (int jj = 0; jj < 4; jj++) {
                    const float kvv = kv[(j0 + (jj << 6)) * 65 + e];
                    #pragma unroll
                    for (int i = 0; i < 4; i++)
                        acc[i][jj] = fmaf(q[i], kvv, acc[i][jj]);
                }
            }
            #pragma unroll
            for (int i = 0; i < 4; i++)
                #pragma unroll
                for (int jj = 0; jj < 4; jj++)
                    sc[(r0 + i) * SS + t0 + j0 + (jj << 6)] = acc[i][jj] * 0.125f;
            __syncthreads();
        }
    }

    // ---- Softmax: warp per 2 rows; keep normalized probs in smem ----
    {
        const int warp = tid >> 5, lane = tid & 31;
        #pragma unroll
        for (int rr = 0; rr < 2; rr++) {
            const int r = warp * 2 + rr;
            float* row = &sc[r * SS];
            float mx = -1e30f;
            for (int t = lane; t < SS; t += 32) mx = fmaxf(mx, row[t]);
            #pragma unroll
            for (int o = 16; o; o >>= 1) mx = fmaxf(mx, __shfl_xor_sync(0xffffffffu, mx, o));
            float sum = 0.f;
            for (int t = lane; t < SS; t += 32) {
                const float ev = __expf(row[t] - mx);
                row[t] = ev;
                sum += ev;
            }
            #pragma unroll
            for (int o = 16; o; o >>= 1) sum += __shfl_xor_sync(0xffffffffu, sum, o);
            const float inv = 1.0f / sum;
            const size_t grow = ((size_t)(h * BB + b) * SS + (s0 + r)) * SS;
            for (int t = lane * 4; t < SS; t += 128) {
                float4 pv = *(float4*)&row[t];
                pv.x *= inv; pv.y *= inv; pv.z *= inv; pv.w *= inv;
                *(float4*)&row[t] = pv;
                if (attn_out) *(float4*)&attn_out[grow + t] = pv;
            }
        }
    }
    __syncthreads();

    // ---- Phase C: weighted = P @ V, 4 t-groups, then reduce ----
    {
        const int g     = tid >> 6;          // t-subgroup 0..3
        const int local = tid & 63;
        const int rc = (local >> 4) << 2;    // 0,4,8,12
        const int e0 = (local & 15) << 2;    // 0..60

        float acc[4][4] = {};
        for (int t0 = 0; t0 < SS; t0 += 256) {
            #pragma unroll
            for (int it = 0; it < 16; it++) {
                const int tl = (it << 4) + (tid >> 4);
                const int ee = (tid & 15) << 2;
                *(float4*)&kv[tl * DHD + ee] =
                    *(const float4*)&vg[(size_t)(t0 + tl) * DD + ee];
            }
            __syncthreads();

            const int tbase = g << 6;
            #pragma unroll 8
            for (int tt = 0; tt < 64; tt++) {
                const int tl = tbase + tt;
                const float4 vv = *(const float4*)&kv[tl * DHD + e0];
                #pragma unroll
                for (int i = 0; i < 4; i++) {
                    const float p = sc[(rc + i) * SS + t0 + tl];
                    acc[i][0] = fmaf(p, vv.x, acc[i][0]);
                    acc[i][1] = fmaf(p, vv.y, acc[i][1]);
                    acc[i][2] = fmaf(p, vv.z, acc[i][2]);
                    acc[i][3] = fmaf(p, vv.w, acc[i][3]);
                }
            }
            __syncthreads();
        }

        // cross-group reduction through sc (fully consumed by now)
        if (g > 0) {
            float* part = sc + (g - 1) * 1024;
            #pragma unroll
            for (int i = 0; i < 4; i++)
                *(float4*)&part[local * 16 + (i << 2)] =
                    make_float4(acc[i][0], acc[i][1], acc[i][2], acc[i][3]);
        }
        __syncthreads();
        if (g == 0) {
            #pragma unroll
            for (int gg = 0; gg < 3; gg++) {
                const float* part = sc + gg * 1024;
                #pragma unroll
                for (int i = 0; i < 4; i++) {
                    const float4 p = *(const float4*)&part[local * 16 + (i << 2)];
                    acc[i][0] += p.x; acc[i][1] += p.y;
                    acc[i][2] += p.z; acc[i][3] += p.w;
                }
            }
            #pragma unroll
            for (int i = 0; i < 4; i++) {
                *(float4*)&g_concat[(size_t)(b * SS + s0 + rc + i) * DD + h * DHD + e0] =
                    make_float4(acc[i][0], acc[i][1], acc[i][2], acc[i][3]);
            }
        }
    }
}

// =====================================================================
// Kernel 3: output = concat @ Wo^T  (NT GEMM, 128x128x8)
// =====================================================================
__global__ __launch_bounds__(256) void gemm_out(
    const float* __restrict__ Wo, float* __restrict__ out)
{
    __shared__ float As[8][128];
    __shared__ float Bs[8][128];

    const int tid  = threadIdx.x;
    const int row0 = blockIdx.x << 7;
    const int col0 = blockIdx.y << 7;
    const int tx = tid & 15, ty = tid >> 4;
    const int m0 = ty << 3, n0 = tx << 3;
    const int lm = tid >> 1;
    const int lk = (tid & 1) << 2;

    float acc[8][8] = {};

    for (int k0 = 0; k0 < DD; k0 += 8) {
        float4 av = *(const float4*)&g_concat[(size_t)(row0 + lm) * DD + k0 + lk];
        As[lk + 0][lm] = av.x; As[lk + 1][lm] = av.y;
        As[lk + 2][lm] = av.z; As[lk + 3][lm] = av.w;
        float4 bv = *(const float4*)&Wo[(size_t)(col0 + lm) * DD + k0 + lk];
        Bs[lk + 0][lm] = bv.x; Bs[lk + 1][lm] = bv.y;
        Bs[lk + 2][lm] = bv.z; Bs[lk + 3][lm] = bv.w;
        __syncthreads();

        #pragma unroll
        for (int k = 0; k < 8; k++) {
            float a[8], b[8];
            *(float4*)&a[0] = *(const float4*)&As[k][m0];
            *(float4*)&a[4] = *(const float4*)&As[k][m0 + 4];
            *(float4*)&b[0] = *(const float4*)&Bs[k][n0];
            *(float4*)&b[4] = *(const float4*)&Bs[k][n0 + 4];
            #pragma unroll
            for (int i = 0; i < 8; i++)
                #pragma unroll
                for (int j = 0; j < 8; j++)
                    acc[i][j] = fmaf(a[i], b[j], acc[i][j]);
        }
        __syncthreads();
    }

    #pragma unroll
    for (int i = 0; i < 8; i++) {
        float* crow = &out[(size_t)(row0 + m0 + i) * DD + col0 + n0];
        *(float4*)&crow[0] = make_float4(acc[i][0], acc[i][1], acc[i][2], acc[i][3]);
        *(float4*)&crow[4] = make_float4(acc[i][4], acc[i][5], acc[i][6], acc[i][7]);
    }
}

// =====================================================================
extern "C" void kernel_launch(void* const* d_in, const int* in_sizes, int n_in,
                              void* d_out, int out_size)
{
    const float* query = (const float*)d_in[0];
    const float* key   = (const float*)d_in[1];
    const float* value = (const float*)d_in[2];
    const float* Wq    = (const float*)d_in[3];
    const float* Wk    = (const float*)d_in[4];
    const float* Wv    = (const float*)d_in[5];
    const float* Wo    = (const float*)d_in[6];
    float* out = (float*)d_out;

    // tuple-flatten assumption: [output (4.19M f32)] [attn (134.2M f32)]
    float* attn_ptr = nullptr;
    if (out_size >= OUT_ELEMS + ATTN_ELEMS) attn_ptr = out + OUT_ELEMS;

    // 1) projections
    gemm_proj<<<dim3(NROWS / 128, DD / 128, 3), 256>>>(query, key, value, Wq, Wk, Wv);

    // 2) fused attention
    const int smem_bytes = (16 * SS + 256 * 65 + 16 * DHD) * (int)sizeof(float); // 201728
    cudaFuncSetAttribute(attn_kernel, cudaFuncAttributeMaxDynamicSharedMemorySize, smem_bytes);
    attn_kernel<<<dim3(SS / 16, BB, HH), 256, smem_bytes>>>(attn_ptr);

    // 3) output projection
    gemm_out<<<dim3(NROWS / 128, DD / 128), 256>>>(Wo, out);
}

// round 5
// speedup vs baseline: 1.7080x; 1.7080x over previous
#include <cuda_runtime.h>
#include <cstdint>

#define BB 2
#define SS 2048
#define DD 1024
#define HH 16
#define DHD 64
#define NROWS (BB*SS)          // 4096
#define OUT_ELEMS (BB*SS*DD)   // 4194304
#define ATTN_ELEMS ((long long)HH*BB*SS*SS) // 134217728

// ---------------- scratch (device globals: allowed) ----------------
__device__ float g_q[NROWS * DD];
__device__ float g_k[NROWS * DD];
__device__ float g_v[NROWS * DD];
__device__ float g_concat[NROWS * DD];

// =====================================================================
// tf32 mma.sync helpers (sm_80+ PTX; compiles on plain sm_103 target)
// =====================================================================
__device__ __forceinline__ uint32_t f2tf32(float f) {
    uint32_t r;
    asm("cvt.rn.tf32.f32 %0, %1;" : "=r"(r) : "f"(f));
    return r;
}
__device__ __forceinline__ void mma_tf32(float c[4], const uint32_t a[4],
                                         uint32_t b0, uint32_t b1) {
    asm volatile(
        "mma.sync.aligned.m16n8k8.row.col.f32.tf32.tf32.f32 "
        "{%0,%1,%2,%3}, {%4,%5,%6,%7}, {%8,%9}, {%0,%1,%2,%3};"
        : "+f"(c[0]), "+f"(c[1]), "+f"(c[2]), "+f"(c[3])
        : "r"(a[0]), "r"(a[1]), "r"(a[2]), "r"(a[3]), "r"(b0), "r"(b1));
}

#define KS_STRIDE 68     // [token][e] rows padded: B-frag reads conflict-free
#define PS_STRIDE 132    // [row][col]: A-frag reads conflict-free
// smem floats: KS 128*68, VS 128*68 (doubles as Q staging), PS 128*132
#define SM_KS 0
#define SM_VS (128*KS_STRIDE)
#define SM_PS (2*128*KS_STRIDE)
#define SM_FLOATS (2*128*KS_STRIDE + 128*PS_STRIDE)   // 34304
#define SMEM_TOTAL_B (SM_FLOATS*4)                    // 137216

// =====================================================================
// Fused attention, mma.sync tf32. CTA = 128 q-rows of one (h,b).
// 8 warps x 16 rows. Two passes over K tiles of 128 tokens.
// =====================================================================
__global__ __launch_bounds__(256, 1) void attn_mma(float* __restrict__ attn_out)
{
    extern __shared__ float sm[];
    float* KS = sm + SM_KS;
    float* VS = sm + SM_VS;
    float* PS = sm + SM_PS;

    const int tid  = threadIdx.x;
    const int wid  = tid >> 5;
    const int lane = tid & 31;
    const int g  = lane >> 2;      // groupID (row within octet)
    const int tg = lane & 3;       // thread-in-group (k index)
    const int m0 = wid << 4;       // warp's 16-row base

    const int s0 = blockIdx.x << 7;
    const int b  = blockIdx.y;
    const int h  = blockIdx.z;

    const float* qg = g_q + (size_t)b * SS * DD + h * DHD;
    const float* kg = g_k + (size_t)b * SS * DD + h * DHD;
    const float* vg = g_v + (size_t)b * SS * DD + h * DHD;

    // ---- stage Q (128x64) into VS as tf32, then load A-fragments ----
    #pragma unroll
    for (int i = 0; i < 8; i++) {
        const int idx = tid + (i << 8);
        const int row = idx >> 4;
        const int e0  = (idx & 15) << 2;
        float4 v = *(const float4*)&qg[(size_t)(s0 + row) * DD + e0];
        uint4 t;
        t.x = f2tf32(v.x); t.y = f2tf32(v.y);
        t.z = f2tf32(v.z); t.w = f2tf32(v.w);
        *(uint4*)&VS[row * KS_STRIDE + e0] = t;
    }
    __syncthreads();

    uint32_t qa[8][4];
    #pragma unroll
    for (int ks = 0; ks < 8; ks++) {
        const int base = (m0 + g) * KS_STRIDE + (ks << 3) + tg;
        qa[ks][0] = __float_as_uint(VS[base]);
        qa[ks][1] = __float_as_uint(VS[base + 8 * KS_STRIDE]);
        qa[ks][2] = __float_as_uint(VS[base + 4]);
        qa[ks][3] = __float_as_uint(VS[base + 8 * KS_STRIDE + 4]);
    }
    __syncthreads();

    // ================= pass 1: row sums =================
    float rlo = 0.f, rhi = 0.f;
    for (int t0i = 0; t0i < 16; t0i++) {
        const int t0 = t0i << 7;
        #pragma unroll
        for (int i = 0; i < 8; i++) {
            const int idx = tid + (i << 8);
            const int row = idx >> 4;
            const int e0  = (idx & 15) << 2;
            float4 v = *(const float4*)&kg[(size_t)(t0 + row) * DD + e0];
            uint4 t;
            t.x = f2tf32(v.x); t.y = f2tf32(v.y);
            t.z = f2tf32(v.z); t.w = f2tf32(v.w);
            *(uint4*)&KS[row * KS_STRIDE + e0] = t;
        }
        __syncthreads();

        #pragma unroll
        for (int nt = 0; nt < 16; nt++) {
            float c[4] = {0.f, 0.f, 0.f, 0.f};
            #pragma unroll
            for (int ks = 0; ks < 8; ks++) {
                const int kb = (((nt << 3) + g) * KS_STRIDE) + (ks << 3) + tg;
                mma_tf32(c, qa[ks],
                         __float_as_uint(KS[kb]),
                         __float_as_uint(KS[kb + 4]));
            }
            rlo += __expf(c[0] * 0.125f) + __expf(c[1] * 0.125f);
            rhi += __expf(c[2] * 0.125f) + __expf(c[3] * 0.125f);
        }
        __syncthreads();
    }
    rlo += __shfl_xor_sync(0xffffffffu, rlo, 1);
    rlo += __shfl_xor_sync(0xffffffffu, rlo, 2);
    rhi += __shfl_xor_sync(0xffffffffu, rhi, 1);
    rhi += __shfl_xor_sync(0xffffffffu, rhi, 2);
    const float inv_lo = 1.0f / rlo;
    const float inv_hi = 1.0f / rhi;

    // ================= pass 2: normalize + attn write + P@V =================
    float oc[8][4];
    #pragma unroll
    for (int nt = 0; nt < 8; nt++)
        #pragma unroll
        for (int j = 0; j < 4; j++) oc[nt][j] = 0.f;

    for (int t0i = 0; t0i < 16; t0i++) {
        const int t0 = t0i << 7;
        // load K tile (tf32)
        #pragma unroll
        for (int i = 0; i < 8; i++) {
            const int idx = tid + (i << 8);
            const int row = idx >> 4;
            const int e0  = (idx & 15) << 2;
            float4 v = *(const float4*)&kg[(size_t)(t0 + row) * DD + e0];
            uint4 t;
            t.x = f2tf32(v.x); t.y = f2tf32(v.y);
            t.z = f2tf32(v.z); t.w = f2tf32(v.w);
            *(uint4*)&KS[row * KS_STRIDE + e0] = t;
        }
        // load V tile (tf32)
        #pragma unroll
        for (int i = 0; i < 8; i++) {
            const int idx = tid + (i << 8);
            const int row = idx >> 4;
            const int e0  = (idx & 15) << 2;
            float4 v = *(const float4*)&vg[(size_t)(t0 + row) * DD + e0];
            uint4 t;
            t.x = f2tf32(v.x); t.y = f2tf32(v.y);
            t.z = f2tf32(v.z); t.w = f2tf32(v.w);
            *(uint4*)&VS[row * KS_STRIDE + e0] = t;
        }
        __syncthreads();

        // scores -> P (normalized, fp32) into PS
        #pragma unroll
        for (int nt = 0; nt < 16; nt++) {
            float c[4] = {0.f, 0.f, 0.f, 0.f};
            #pragma unroll
            for (int ks = 0; ks < 8; ks++) {
                const int kb = (((nt << 3) + g) * KS_STRIDE) + (ks << 3) + tg;
                mma_tf32(c, qa[ks],
                         __float_as_uint(KS[kb]),
                         __float_as_uint(KS[kb + 4]));
            }
            const int row = m0 + g;
            const int col = (nt << 3) + (tg << 1);
            *(float2*)&PS[row * PS_STRIDE + col] =
                make_float2(__expf(c[0] * 0.125f) * inv_lo,
                            __expf(c[1] * 0.125f) * inv_lo);
            *(float2*)&PS[(row + 8) * PS_STRIDE + col] =
                make_float2(__expf(c[2] * 0.125f) * inv_hi,
                            __expf(c[3] * 0.125f) * inv_hi);
        }
        __syncthreads();

        // O += P @ V   (A-frags from PS, B-frags from VS)
        #pragma unroll
        for (int ks = 0; ks < 16; ks++) {
            uint32_t a[4];
            const int base = (m0 + g) * PS_STRIDE + (ks << 3) + tg;
            a[0] = __float_as_uint(PS[base]);
            a[1] = __float_as_uint(PS[base + 8 * PS_STRIDE]);
            a[2] = __float_as_uint(PS[base + 4]);
            a[3] = __float_as_uint(PS[base + 8 * PS_STRIDE + 4]);
            #pragma unroll
            for (int nt = 0; nt < 8; nt++) {
                const int vb0 = ((ks << 3) + tg) * KS_STRIDE + (nt << 3) + g;
                mma_tf32(oc[nt], a,
                         __float_as_uint(VS[vb0]),
                         __float_as_uint(VS[vb0 + 4 * KS_STRIDE]));
            }
        }

        // write normalized attn tile (each warp writes full 128-float rows)
        if (attn_out) {
            const size_t gbase = ((size_t)(h * BB + b) * SS + s0) * SS + t0;
            #pragma unroll
            for (int i = 0; i < 16; i++) {
                const int lin = tid + (i << 8);
                const int row = lin >> 5;
                const int c4  = (lin & 31) << 2;
                float4 pv = *(const float4*)&PS[row * PS_STRIDE + c4];
                *(float4*)&attn_out[gbase + (size_t)row * SS + c4] = pv;
            }
        }
        __syncthreads();
    }

    // ---- write O (128 x 64) to g_concat ----
    {
        const size_t row = (size_t)(b * SS + s0 + m0 + g);
        #pragma unroll
        for (int nt = 0; nt < 8; nt++) {
            const int col = h * DHD + (nt << 3) + (tg << 1);
            *(float2*)&g_concat[row * DD + col] =
                make_float2(oc[nt][0], oc[nt][1]);
            *(float2*)&g_concat[(row + 8) * DD + col] =
                make_float2(oc[nt][2], oc[nt][3]);
        }
    }
}

// =====================================================================
// Kernel 1: per-head projections (fp32 SIMT, known-good from R2)
// =====================================================================
__global__ __launch_bounds__(256) void gemm_proj(
    const float* __restrict__ q_in, const float* __restrict__ k_in,
    const float* __restrict__ v_in,
    const float* __restrict__ Wq, const float* __restrict__ Wk,
    const float* __restrict__ Wv)
{
    const int z = blockIdx.z;
    const float* A = (z == 0) ? q_in : ((z == 1) ? k_in : v_in);
    const float* W = (z == 0) ? Wq   : ((z == 1) ? Wk   : Wv);
    float* C       = (z == 0) ? g_q  : ((z == 1) ? g_k  : g_v);

    __shared__ float As[8][128];
    __shared__ float Bs[8][128];

    const int tid  = threadIdx.x;
    const int row0 = blockIdx.x << 7;
    const int col0 = blockIdx.y << 7;
    const int tx = tid & 15, ty = tid >> 4;
    const int m0 = ty << 3, n0 = tx << 3;
    const int lm = tid >> 1;
    const int lk = (tid & 1) << 2;
    const int bk = tid >> 5;
    const int bn = (tid & 31) << 2;

    float acc[8][8] = {};

    for (int k0 = 0; k0 < DD; k0 += 8) {
        float4 av = *(const float4*)&A[(size_t)(row0 + lm) * DD + k0 + lk];
        As[lk + 0][lm] = av.x; As[lk + 1][lm] = av.y;
        As[lk + 2][lm] = av.z; As[lk + 3][lm] = av.w;

        const int n = col0 + bn;
        const int widx = ((n >> 6) * DD + (k0 + bk)) * DHD + (n & 63);
        *(float4*)&Bs[bk][bn] = *(const float4*)&W[widx];
        __syncthreads();

        #pragma unroll
        for (int k = 0; k < 8; k++) {
            float a[8], bb[8];
            *(float4*)&a[0] = *(const float4*)&As[k][m0];
            *(float4*)&a[4] = *(const float4*)&As[k][m0 + 4];
            *(float4*)&bb[0] = *(const float4*)&Bs[k][n0];
            *(float4*)&bb[4] = *(const float4*)&Bs[k][n0 + 4];
            #pragma unroll
            for (int i = 0; i < 8; i++)
                #pragma unroll
                for (int j = 0; j < 8; j++)
                    acc[i][j] = fmaf(a[i], bb[j], acc[i][j]);
        }
        __syncthreads();
    }

    #pragma unroll
    for (int i = 0; i < 8; i++) {
        float* crow = &C[(size_t)(row0 + m0 + i) * DD + col0 + n0];
        *(float4*)&crow[0] = make_float4(acc[i][0], acc[i][1], acc[i][2], acc[i][3]);
        *(float4*)&crow[4] = make_float4(acc[i][4], acc[i][5], acc[i][6], acc[i][7]);
    }
}

// =====================================================================
// Kernel 3: output = concat @ Wo^T (fp32 SIMT, known-good from R2)
// =====================================================================
__global__ __launch_bounds__(256) void gemm_out(
    const float* __restrict__ Wo, float* __restrict__ out)
{
    __shared__ float As[8][128];
    __shared__ float Bs[8][128];

    const int tid  = threadIdx.x;
    const int row0 = blockIdx.x << 7;
    const int col0 = blockIdx.y << 7;
    const int tx = tid & 15, ty = tid >> 4;
    const int m0 = ty << 3, n0 = tx << 3;
    const int lm = tid >> 1;
    const int lk = (tid & 1) << 2;

    float acc[8][8] = {};

    for (int k0 = 0; k0 < DD; k0 += 8) {
        float4 av = *(const float4*)&g_concat[(size_t)(row0 + lm) * DD + k0 + lk];
        As[lk + 0][lm] = av.x; As[lk + 1][lm] = av.y;
        As[lk + 2][lm] = av.z; As[lk + 3][lm] = av.w;
        float4 bv = *(const float4*)&Wo[(size_t)(col0 + lm) * DD + k0 + lk];
        Bs[lk + 0][lm] = bv.x; Bs[lk + 1][lm] = bv.y;
        Bs[lk + 2][lm] = bv.z; Bs[lk + 3][lm] = bv.w;
        __syncthreads();

        #pragma unroll
        for (int k = 0; k < 8; k++) {
            float a[8], bb[8];
            *(float4*)&a[0] = *(const float4*)&As[k][m0];
            *(float4*)&a[4] = *(const float4*)&As[k][m0 + 4];
            *(float4*)&bb[0] = *(const float4*)&Bs[k][n0];
            *(float4*)&bb[4] = *(const float4*)&Bs[k][n0 + 4];
            #pragma unroll
            for (int i = 0; i < 8; i++)
                #pragma unroll
                for (int j = 0; j < 8; j++)
                    acc[i][j] = fmaf(a[i], bb[j], acc[i][j]);
        }
        __syncthreads();
    }

    #pragma unroll
    for (int i = 0; i < 8; i++) {
        float* crow = &out[(size_t)(row0 + m0 + i) * DD + col0 + n0];
        *(float4*)&crow[0] = make_float4(acc[i][0], acc[i][1], acc[i][2], acc[i][3]);
        *(float4*)&crow[4] = make_float4(acc[i][4], acc[i][5], acc[i][6], acc[i][7]);
    }
}

// =====================================================================
extern "C" void kernel_launch(void* const* d_in, const int* in_sizes, int n_in,
                              void* d_out, int out_size)
{
    const float* query = (const float*)d_in[0];
    const float* key   = (const float*)d_in[1];
    const float* value = (const float*)d_in[2];
    const float* Wq    = (const float*)d_in[3];
    const float* Wk    = (const float*)d_in[4];
    const float* Wv    = (const float*)d_in[5];
    const float* Wo    = (const float*)d_in[6];
    float* out = (float*)d_out;

    float* attn_ptr = nullptr;
    if ((long long)out_size >= (long long)OUT_ELEMS + ATTN_ELEMS)
        attn_ptr = out + OUT_ELEMS;

    // 1) projections (fp32 SIMT)
    gemm_proj<<<dim3(NROWS / 128, DD / 128, 3), 256>>>(query, key, value, Wq, Wk, Wv);

    // 2) fused attention (mma.sync tf32)
    cudaFuncSetAttribute(attn_mma, cudaFuncAttributeMaxDynamicSharedMemorySize,
                         SMEM_TOTAL_B);
    attn_mma<<<dim3(SS / 128, BB, HH), 256, SMEM_TOTAL_B>>>(attn_ptr);

    // 3) output projection (fp32 SIMT)
    gemm_out<<<dim3(NROWS / 128, DD / 128), 256>>>(Wo, out);
}